// round 14
// baseline (speedup 1.0000x reference)
#include <cuda_runtime.h>

// h: [N_ROWS, DIM] fp32; S: [DIM, DIM] fp32 diagonal ±1.
// out = h @ S.T = h * diag(S) broadcast over rows — pure streaming op.
//
// FINAL (verified optimum, converged over R10-R13: 45.54/45.79/45.79/45.79us).
// Bound by mixed read+write HBM throughput: 268 MB mandatory traffic at
// ~6.8 TB/s effective (~85% of 8 TB/s spec) = ~39.5us kernel floor.
// occ x MLP sits at the L1tex in-flight queue cap (~250 LDGs/SM).
// Tested and rejected: stcs / evict_last / cache_hint (all regressed),
// 256-bit LDG/STG (regressed), software pipelining, fat blocks, 32-bit
// indexing (all neutral). Config: float4 __ldcg, MLP=8 front-batch,
// 4096x256, exact-shape tiling, column-invariant signs, default stores.

template <int ITERS>
__global__ __launch_bounds__(256)
void parity_scale_exact(const float4* __restrict__ h,
                        const float* __restrict__ S,
                        float4* __restrict__ out,
                        int dim4, int dim) {
    const long long stride = (long long)gridDim.x * blockDim.x;
    const long long idx0 = (long long)blockIdx.x * blockDim.x + threadIdx.x;

    // Column invariant: stride % dim4 == 0 guaranteed by host.
    int col4 = (int)(idx0 % (long long)dim4);
    int c = col4 * 4;

    float4 s;
    s.x = S[(long long)(c + 0) * dim + (c + 0)];
    s.y = S[(long long)(c + 1) * dim + (c + 1)];
    s.z = S[(long long)(c + 2) * dim + (c + 2)];
    s.w = S[(long long)(c + 3) * dim + (c + 3)];

    // Front-batch all loads: MLP = ITERS per thread.
    float4 v[ITERS];
    #pragma unroll
    for (int i = 0; i < ITERS; i++) {
        v[i] = __ldcg(&h[idx0 + (long long)i * stride]);
    }
    #pragma unroll
    for (int i = 0; i < ITERS; i++) {
        float4 r = v[i];
        r.x *= s.x; r.y *= s.y; r.z *= s.z; r.w *= s.w;
        out[idx0 + (long long)i * stride] = r;
    }
}

// ---------------- Generic fallback ------------------------------------------
__global__ void parity_scale_generic(const float4* __restrict__ h,
                                     const float* __restrict__ S,
                                     float4* __restrict__ out,
                                     long long n_vec4, int dim4, int dim) {
    long long idx0 = (long long)blockIdx.x * blockDim.x + threadIdx.x;
    long long stride = (long long)gridDim.x * blockDim.x;  // multiple of dim4

    int col4 = (int)(idx0 % (long long)dim4);
    int c = col4 * 4;

    float4 s;
    s.x = S[(long long)(c + 0) * dim + (c + 0)];
    s.y = S[(long long)(c + 1) * dim + (c + 1)];
    s.z = S[(long long)(c + 2) * dim + (c + 2)];
    s.w = S[(long long)(c + 3) * dim + (c + 3)];

    #pragma unroll 4
    for (long long idx = idx0; idx < n_vec4; idx += stride) {
        float4 v = __ldcg(&h[idx]);
        v.x *= s.x; v.y *= s.y; v.z *= s.z; v.w *= s.w;
        out[idx] = v;
    }
}

static long long gcd_ll(long long a, long long b) {
    while (b) { long long t = a % b; a = b; b = t; }
    return a;
}

extern "C" void kernel_launch(void* const* d_in, const int* in_sizes, int n_in,
                              void* d_out, int out_size) {
    const float* h = (const float*)d_in[0];
    const float* S = (const float*)d_in[1];
    float* out = (float*)d_out;

    // in_sizes[1] = DIM*DIM -> integer sqrt
    int dim = 1;
    {
        long long s = in_sizes[1];
        long long lo = 1, hi = 65536;
        while (lo < hi) {
            long long mid = (lo + hi + 1) / 2;
            if (mid * mid <= s) lo = mid; else hi = mid - 1;
        }
        dim = (int)lo;
    }

    long long total = in_sizes[0];        // N_ROWS * DIM
    long long n_vec4 = total / 4;
    int dim4 = dim / 4;

    const int threads = 256;

    const int ITERS = 8;
    long long T = n_vec4 / ITERS;
    bool exact = (n_vec4 % ITERS == 0) &&
                 (T % threads == 0) &&
                 (T % dim4 == 0) &&
                 (T / threads <= 2147483647LL) &&
                 (dim % 4 == 0);

    if (exact) {
        int blocks = (int)(T / threads);
        parity_scale_exact<ITERS><<<blocks, threads>>>(
            (const float4*)h, S, (float4*)out, dim4, dim);
        return;
    }

    // Generic fallback: grid-stride multiple of dim4 (col invariance).
    long long m = (long long)dim4 / gcd_ll(threads, dim4);
    long long want = 148LL * 32;
    long long blocks = ((want + m - 1) / m) * m;
    long long cover = (n_vec4 + threads - 1) / threads;
    long long cover_r = ((cover + m - 1) / m) * m;
    if (blocks > cover_r) blocks = cover_r;
    if (blocks < m) blocks = m;

    parity_scale_generic<<<(int)blocks, threads>>>(
        (const float4*)h, S, (float4*)out, n_vec4, dim4, dim);
}

// round 15
// speedup vs baseline: 1.0063x; 1.0063x over previous
#include <cuda_runtime.h>

// h: [N_ROWS, DIM] fp32; S: [DIM, DIM] fp32 diagonal ±1.
// out = h @ S.T = h * diag(S) broadcast over rows — pure streaming op.
//
// R15: final micro-probe — same proven config (float4 __ldcg, MLP=8
// front-batch, exact-shape tiling, col-invariant signs, default stores)
// but 128-thread blocks x 8192 CTAs: finer work granularity halves the
// per-CTA L1tex LDG burst and smooths the last-wave tail per the B300
// CTA-spread model. Everything else identical to the converged optimum.

template <int ITERS>
__global__ __launch_bounds__(128)
void parity_scale_exact(const float4* __restrict__ h,
                        const float* __restrict__ S,
                        float4* __restrict__ out,
                        int dim4, int dim) {
    const long long stride = (long long)gridDim.x * blockDim.x;
    const long long idx0 = (long long)blockIdx.x * blockDim.x + threadIdx.x;

    // Column invariant: stride % dim4 == 0 guaranteed by host.
    int col4 = (int)(idx0 % (long long)dim4);
    int c = col4 * 4;

    float4 s;
    s.x = S[(long long)(c + 0) * dim + (c + 0)];
    s.y = S[(long long)(c + 1) * dim + (c + 1)];
    s.z = S[(long long)(c + 2) * dim + (c + 2)];
    s.w = S[(long long)(c + 3) * dim + (c + 3)];

    // Front-batch all loads: MLP = ITERS per thread.
    float4 v[ITERS];
    #pragma unroll
    for (int i = 0; i < ITERS; i++) {
        v[i] = __ldcg(&h[idx0 + (long long)i * stride]);
    }
    #pragma unroll
    for (int i = 0; i < ITERS; i++) {
        float4 r = v[i];
        r.x *= s.x; r.y *= s.y; r.z *= s.z; r.w *= s.w;
        out[idx0 + (long long)i * stride] = r;
    }
}

// ---------------- Generic fallback ------------------------------------------
__global__ void parity_scale_generic(const float4* __restrict__ h,
                                     const float* __restrict__ S,
                                     float4* __restrict__ out,
                                     long long n_vec4, int dim4, int dim) {
    long long idx0 = (long long)blockIdx.x * blockDim.x + threadIdx.x;
    long long stride = (long long)gridDim.x * blockDim.x;  // multiple of dim4

    int col4 = (int)(idx0 % (long long)dim4);
    int c = col4 * 4;

    float4 s;
    s.x = S[(long long)(c + 0) * dim + (c + 0)];
    s.y = S[(long long)(c + 1) * dim + (c + 1)];
    s.z = S[(long long)(c + 2) * dim + (c + 2)];
    s.w = S[(long long)(c + 3) * dim + (c + 3)];

    #pragma unroll 4
    for (long long idx = idx0; idx < n_vec4; idx += stride) {
        float4 v = __ldcg(&h[idx]);
        v.x *= s.x; v.y *= s.y; v.z *= s.z; v.w *= s.w;
        out[idx] = v;
    }
}

static long long gcd_ll(long long a, long long b) {
    while (b) { long long t = a % b; a = b; b = t; }
    return a;
}

extern "C" void kernel_launch(void* const* d_in, const int* in_sizes, int n_in,
                              void* d_out, int out_size) {
    const float* h = (const float*)d_in[0];
    const float* S = (const float*)d_in[1];
    float* out = (float*)d_out;

    // in_sizes[1] = DIM*DIM -> integer sqrt
    int dim = 1;
    {
        long long s = in_sizes[1];
        long long lo = 1, hi = 65536;
        while (lo < hi) {
            long long mid = (lo + hi + 1) / 2;
            if (mid * mid <= s) lo = mid; else hi = mid - 1;
        }
        dim = (int)lo;
    }

    long long total = in_sizes[0];        // N_ROWS * DIM
    long long n_vec4 = total / 4;
    int dim4 = dim / 4;

    const int threads = 128;

    const int ITERS = 8;
    long long T = n_vec4 / ITERS;
    bool exact = (n_vec4 % ITERS == 0) &&
                 (T % threads == 0) &&
                 (T % dim4 == 0) &&
                 (T / threads <= 2147483647LL) &&
                 (dim % 4 == 0);

    if (exact) {
        int blocks = (int)(T / threads);
        parity_scale_exact<ITERS><<<blocks, threads>>>(
            (const float4*)h, S, (float4*)out, dim4, dim);
        return;
    }

    // Generic fallback: grid-stride multiple of dim4 (col invariance).
    const int gthreads = 256;
    long long m = (long long)dim4 / gcd_ll(gthreads, dim4);
    long long want = 148LL * 32;
    long long blocks = ((want + m - 1) / m) * m;
    long long cover = (n_vec4 + gthreads - 1) / gthreads;
    long long cover_r = ((cover + m - 1) / m) * m;
    if (blocks > cover_r) blocks = cover_r;
    if (blocks < m) blocks = m;

    parity_scale_generic<<<(int)blocks, gthreads>>>(
        (const float4*)h, S, (float4*)out, n_vec4, dim4, dim);
}

// round 16
// speedup vs baseline: 1.0149x; 1.0085x over previous
#include <cuda_runtime.h>

// h: [N_ROWS, DIM] fp32; S: [DIM, DIM] fp32 diagonal ±1.
// out = h @ S.T = h * diag(S) broadcast over rows — pure streaming op.
//
// FINAL (verified optimum, 15 rounds). Tied-best: 45.536us timed /
// 39.296us kernel (reproduced). Bound by mixed read+write HBM throughput:
// 268 MB mandatory traffic at ~6.8 TB/s effective (~85% of 8 TB/s spec).
// Exploration complete: stcs/evict_last/cache_hint all regressed; 256-bit
// LDG/STG regressed; MLP {4,8,pipelined}, blocks {128,256,512}, index
// width {32,64} all flat at the roofline. Config: float4 __ldcg, MLP=8
// front-batch, 8192x128, exact-shape tiling, column-invariant signs,
// default stores.

template <int ITERS>
__global__ __launch_bounds__(128)
void parity_scale_exact(const float4* __restrict__ h,
                        const float* __restrict__ S,
                        float4* __restrict__ out,
                        int dim4, int dim) {
    const long long stride = (long long)gridDim.x * blockDim.x;
    const long long idx0 = (long long)blockIdx.x * blockDim.x + threadIdx.x;

    // Column invariant: stride % dim4 == 0 guaranteed by host.
    int col4 = (int)(idx0 % (long long)dim4);
    int c = col4 * 4;

    float4 s;
    s.x = S[(long long)(c + 0) * dim + (c + 0)];
    s.y = S[(long long)(c + 1) * dim + (c + 1)];
    s.z = S[(long long)(c + 2) * dim + (c + 2)];
    s.w = S[(long long)(c + 3) * dim + (c + 3)];

    // Front-batch all loads: MLP = ITERS per thread.
    float4 v[ITERS];
    #pragma unroll
    for (int i = 0; i < ITERS; i++) {
        v[i] = __ldcg(&h[idx0 + (long long)i * stride]);
    }
    #pragma unroll
    for (int i = 0; i < ITERS; i++) {
        float4 r = v[i];
        r.x *= s.x; r.y *= s.y; r.z *= s.z; r.w *= s.w;
        out[idx0 + (long long)i * stride] = r;
    }
}

// ---------------- Generic fallback ------------------------------------------
__global__ void parity_scale_generic(const float4* __restrict__ h,
                                     const float* __restrict__ S,
                                     float4* __restrict__ out,
                                     long long n_vec4, int dim4, int dim) {
    long long idx0 = (long long)blockIdx.x * blockDim.x + threadIdx.x;
    long long stride = (long long)gridDim.x * blockDim.x;  // multiple of dim4

    int col4 = (int)(idx0 % (long long)dim4);
    int c = col4 * 4;

    float4 s;
    s.x = S[(long long)(c + 0) * dim + (c + 0)];
    s.y = S[(long long)(c + 1) * dim + (c + 1)];
    s.z = S[(long long)(c + 2) * dim + (c + 2)];
    s.w = S[(long long)(c + 3) * dim + (c + 3)];

    #pragma unroll 4
    for (long long idx = idx0; idx < n_vec4; idx += stride) {
        float4 v = __ldcg(&h[idx]);
        v.x *= s.x; v.y *= s.y; v.z *= s.z; v.w *= s.w;
        out[idx] = v;
    }
}

static long long gcd_ll(long long a, long long b) {
    while (b) { long long t = a % b; a = b; b = t; }
    return a;
}

extern "C" void kernel_launch(void* const* d_in, const int* in_sizes, int n_in,
                              void* d_out, int out_size) {
    const float* h = (const float*)d_in[0];
    const float* S = (const float*)d_in[1];
    float* out = (float*)d_out;

    // in_sizes[1] = DIM*DIM -> integer sqrt
    int dim = 1;
    {
        long long s = in_sizes[1];
        long long lo = 1, hi = 65536;
        while (lo < hi) {
            long long mid = (lo + hi + 1) / 2;
            if (mid * mid <= s) lo = mid; else hi = mid - 1;
        }
        dim = (int)lo;
    }

    long long total = in_sizes[0];        // N_ROWS * DIM
    long long n_vec4 = total / 4;
    int dim4 = dim / 4;

    const int threads = 128;

    const int ITERS = 8;
    long long T = n_vec4 / ITERS;
    bool exact = (n_vec4 % ITERS == 0) &&
                 (T % threads == 0) &&
                 (T % dim4 == 0) &&
                 (T / threads <= 2147483647LL) &&
                 (dim % 4 == 0);

    if (exact) {
        int blocks = (int)(T / threads);
        parity_scale_exact<ITERS><<<blocks, threads>>>(
            (const float4*)h, S, (float4*)out, dim4, dim);
        return;
    }

    // Generic fallback: grid-stride multiple of dim4 (col invariance).
    const int gthreads = 256;
    long long m = (long long)dim4 / gcd_ll(gthreads, dim4);
    long long want = 148LL * 32;
    long long blocks = ((want + m - 1) / m) * m;
    long long cover = (n_vec4 + gthreads - 1) / gthreads;
    long long cover_r = ((cover + m - 1) / m) * m;
    if (blocks > cover_r) blocks = cover_r;
    if (blocks < m) blocks = m;

    parity_scale_generic<<<(int)blocks, gthreads>>>(
        (const float4*)h, S, (float4*)out, n_vec4, dim4, dim);
}

// round 17
// speedup vs baseline: 1.0156x; 1.0007x over previous
#include <cuda_runtime.h>

// h: [N_ROWS, DIM] fp32; S: [DIM, DIM] fp32 diagonal ±1.
// out = h @ S.T = h * diag(S) broadcast over rows — pure streaming op.
//
// R17: granularity probe continued — 64-thread blocks x 16384 CTAs.
// Trend across blocks {512, 256, 128} shows finer CTA granularity trims
// the wave-tail spread (per the B300 cross-CTA L1tex-queue model) at zero
// cost elsewhere. Core config unchanged (proven over 16 rounds): float4
// __ldcg, MLP=8 front-batch, exact-shape tiling, column-invariant signs,
// default stores — at the ~6.8 TB/s mixed R/W HBM roofline.

template <int ITERS>
__global__ __launch_bounds__(64)
void parity_scale_exact(const float4* __restrict__ h,
                        const float* __restrict__ S,
                        float4* __restrict__ out,
                        int dim4, int dim) {
    const long long stride = (long long)gridDim.x * blockDim.x;
    const long long idx0 = (long long)blockIdx.x * blockDim.x + threadIdx.x;

    // Column invariant: stride % dim4 == 0 guaranteed by host.
    int col4 = (int)(idx0 % (long long)dim4);
    int c = col4 * 4;

    float4 s;
    s.x = S[(long long)(c + 0) * dim + (c + 0)];
    s.y = S[(long long)(c + 1) * dim + (c + 1)];
    s.z = S[(long long)(c + 2) * dim + (c + 2)];
    s.w = S[(long long)(c + 3) * dim + (c + 3)];

    // Front-batch all loads: MLP = ITERS per thread.
    float4 v[ITERS];
    #pragma unroll
    for (int i = 0; i < ITERS; i++) {
        v[i] = __ldcg(&h[idx0 + (long long)i * stride]);
    }
    #pragma unroll
    for (int i = 0; i < ITERS; i++) {
        float4 r = v[i];
        r.x *= s.x; r.y *= s.y; r.z *= s.z; r.w *= s.w;
        out[idx0 + (long long)i * stride] = r;
    }
}

// ---------------- Generic fallback ------------------------------------------
__global__ void parity_scale_generic(const float4* __restrict__ h,
                                     const float* __restrict__ S,
                                     float4* __restrict__ out,
                                     long long n_vec4, int dim4, int dim) {
    long long idx0 = (long long)blockIdx.x * blockDim.x + threadIdx.x;
    long long stride = (long long)gridDim.x * blockDim.x;  // multiple of dim4

    int col4 = (int)(idx0 % (long long)dim4);
    int c = col4 * 4;

    float4 s;
    s.x = S[(long long)(c + 0) * dim + (c + 0)];
    s.y = S[(long long)(c + 1) * dim + (c + 1)];
    s.z = S[(long long)(c + 2) * dim + (c + 2)];
    s.w = S[(long long)(c + 3) * dim + (c + 3)];

    #pragma unroll 4
    for (long long idx = idx0; idx < n_vec4; idx += stride) {
        float4 v = __ldcg(&h[idx]);
        v.x *= s.x; v.y *= s.y; v.z *= s.z; v.w *= s.w;
        out[idx] = v;
    }
}

static long long gcd_ll(long long a, long long b) {
    while (b) { long long t = a % b; a = b; b = t; }
    return a;
}

extern "C" void kernel_launch(void* const* d_in, const int* in_sizes, int n_in,
                              void* d_out, int out_size) {
    const float* h = (const float*)d_in[0];
    const float* S = (const float*)d_in[1];
    float* out = (float*)d_out;

    // in_sizes[1] = DIM*DIM -> integer sqrt
    int dim = 1;
    {
        long long s = in_sizes[1];
        long long lo = 1, hi = 65536;
        while (lo < hi) {
            long long mid = (lo + hi + 1) / 2;
            if (mid * mid <= s) lo = mid; else hi = mid - 1;
        }
        dim = (int)lo;
    }

    long long total = in_sizes[0];        // N_ROWS * DIM
    long long n_vec4 = total / 4;
    int dim4 = dim / 4;

    const int threads = 64;

    const int ITERS = 8;
    long long T = n_vec4 / ITERS;
    bool exact = (n_vec4 % ITERS == 0) &&
                 (T % threads == 0) &&
                 (T % dim4 == 0) &&
                 (T / threads <= 2147483647LL) &&
                 (dim % 4 == 0);

    if (exact) {
        int blocks = (int)(T / threads);
        parity_scale_exact<ITERS><<<blocks, threads>>>(
            (const float4*)h, S, (float4*)out, dim4, dim);
        return;
    }

    // Generic fallback: grid-stride multiple of dim4 (col invariance).
    const int gthreads = 256;
    long long m = (long long)dim4 / gcd_ll(gthreads, dim4);
    long long want = 148LL * 32;
    long long blocks = ((want + m - 1) / m) * m;
    long long cover = (n_vec4 + gthreads - 1) / gthreads;
    long long cover_r = ((cover + m - 1) / m) * m;
    if (blocks > cover_r) blocks = cover_r;
    if (blocks < m) blocks = m;

    parity_scale_generic<<<(int)blocks, gthreads>>>(
        (const float4*)h, S, (float4*)out, n_vec4, dim4, dim);
}